// round 9
// baseline (speedup 1.0000x reference)
#include <cuda_runtime.h>
#include <cstdint>

#define BATCH 64
#define SEQ   1024
#define IDIM  256
#define HDIM  512
#define ODIM  128
#define G4    2048

// ---------------- device scratch ----------------
__device__ float g_xp[(size_t)SEQ * BATCH * G4];       // forward input projection [t*64+b][4H]
__device__ float g_h[2][BATCH * HDIM];                 // double-buffered hidden state
__device__ float g_last[BATCH * 2 * HDIM];
__device__ unsigned long long g_flags[128][16];        // padded per-block barrier flags (128B rows)

typedef unsigned long long ull;

__device__ __forceinline__ void ffma2(ull &acc, ull a, ull b) {
    asm("fma.rn.f32x2 %0, %1, %2, %0;" : "+l"(acc) : "l"(a), "l"(b));
}
__device__ __forceinline__ float2 unpack2(ull v) {
    float2 f; asm("mov.b64 {%0, %1}, %2;" : "=f"(f.x), "=f"(f.y) : "l"(v)); return f;
}
__device__ __forceinline__ ull dup2(float a) {
    ull r; asm("mov.b64 %0, {%1, %1};" : "=l"(r) : "f"(a)); return r;
}
// fast activations: __expf (MUFU.EX2 path) + approx divide. rel err ~2^-21.
__device__ __forceinline__ float sigf(float v) {
    return __fdividef(1.0f, 1.0f + __expf(-v));
}
__device__ __forceinline__ float tanhf_fast(float v) {
    float e = __expf(2.0f * v);
    return __fdividef(e - 1.0f, e + 1.0f);
}

// ================================================================
// Kernel 1: xp = relu(x) @ W_ih_f^T + b_f   (M=65536, N=2048, K=256)
// 128x64x32 tiles, double-buffered, 8x4 microtile with f32x2.
// ================================================================
#define BM 128
#define BN 64
#define BK 32
#define ALD 132
#define BLD 68
#define GEMM_SMEM ((2*BK*ALD + 2*BK*BLD) * 4)

__global__ void __launch_bounds__(256, 2) gemm_xp_kernel(
    const float* __restrict__ x,
    const float* __restrict__ Wih, const float* __restrict__ bias)
{
    extern __shared__ float smg[];
    float* As = smg;                 // [2][BK][ALD]   [k][m]
    float* Bs = smg + 2 * BK * ALD;  // [2][BK][BLD]   [k][n]

    const int tid = threadIdx.x;
    const int n0  = blockIdx.x * BN;
    const int t0  = blockIdx.y * 2;
    const int tx  = tid & 15;        // n group (4 cols)
    const int ty  = tid >> 4;        // m group (8 rows)

    const int mA = tid >> 3, kqA = tid & 7;
    const float* aptr[4];
#pragma unroll
    for (int i = 0; i < 4; i++) {
        int m = mA + i * 32;
        aptr[i] = x + ((size_t)(m & 63) * SEQ + t0 + (m >> 6)) * IDIM + kqA * 4;
    }
    const int nB = tid >> 3, kqB = tid & 7;
    const float* bptr[2];
#pragma unroll
    for (int i = 0; i < 2; i++)
        bptr[i] = Wih + (size_t)(n0 + nB + i * 32) * IDIM + kqB * 4;

    ull acc[8][2];
#pragma unroll
    for (int i = 0; i < 8; i++) { acc[i][0] = 0; acc[i][1] = 0; }

    float4 ra[4], rb[2];
#pragma unroll
    for (int i = 0; i < 4; i++) ra[i] = *(const float4*)(aptr[i]);
#pragma unroll
    for (int i = 0; i < 2; i++) rb[i] = *(const float4*)(bptr[i]);

#define STSAB(BUF) do{                                                     \
    float* ab = As + (BUF) * BK * ALD;                                     \
    _Pragma("unroll") for (int i = 0; i < 4; i++) {                        \
        int m = mA + i * 32;                                               \
        ab[(kqA*4+0)*ALD + m] = fmaxf(ra[i].x, 0.f);                       \
        ab[(kqA*4+1)*ALD + m] = fmaxf(ra[i].y, 0.f);                       \
        ab[(kqA*4+2)*ALD + m] = fmaxf(ra[i].z, 0.f);                       \
        ab[(kqA*4+3)*ALD + m] = fmaxf(ra[i].w, 0.f); }                     \
    float* bb = Bs + (BUF) * BK * BLD;                                     \
    _Pragma("unroll") for (int i = 0; i < 2; i++) {                        \
        int n = nB + i * 32;                                               \
        bb[(kqB*4+0)*BLD + n] = rb[i].x; bb[(kqB*4+1)*BLD + n] = rb[i].y;  \
        bb[(kqB*4+2)*BLD + n] = rb[i].z; bb[(kqB*4+3)*BLD + n] = rb[i].w; }\
}while(0)

    STSAB(0);
    __syncthreads();

    int buf = 0;
#pragma unroll 1
    for (int it = 0; it < 8; it++) {
        if (it < 7) {
#pragma unroll
            for (int i = 0; i < 4; i++) ra[i] = *(const float4*)(aptr[i] + (it + 1) * BK);
#pragma unroll
            for (int i = 0; i < 2; i++) rb[i] = *(const float4*)(bptr[i] + (it + 1) * BK);
        }
        {
            const float* ab = As + buf * BK * ALD + ty * 8;
            const float* bb = Bs + buf * BK * BLD + tx * 4;
#pragma unroll
            for (int k = 0; k < BK; k++) {
                float4 a0 = *(const float4*)(ab + k * ALD);
                float4 a1 = *(const float4*)(ab + k * ALD + 4);
                ulonglong2 bq = *(const ulonglong2*)(bb + k * BLD);
                ull ad;
                ad = dup2(a0.x); ffma2(acc[0][0], ad, bq.x); ffma2(acc[0][1], ad, bq.y);
                ad = dup2(a0.y); ffma2(acc[1][0], ad, bq.x); ffma2(acc[1][1], ad, bq.y);
                ad = dup2(a0.z); ffma2(acc[2][0], ad, bq.x); ffma2(acc[2][1], ad, bq.y);
                ad = dup2(a0.w); ffma2(acc[3][0], ad, bq.x); ffma2(acc[3][1], ad, bq.y);
                ad = dup2(a1.x); ffma2(acc[4][0], ad, bq.x); ffma2(acc[4][1], ad, bq.y);
                ad = dup2(a1.y); ffma2(acc[5][0], ad, bq.x); ffma2(acc[5][1], ad, bq.y);
                ad = dup2(a1.z); ffma2(acc[6][0], ad, bq.x); ffma2(acc[6][1], ad, bq.y);
                ad = dup2(a1.w); ffma2(acc[7][0], ad, bq.x); ffma2(acc[7][1], ad, bq.y);
            }
        }
        if (it < 7) {
            STSAB(buf ^ 1);
            __syncthreads();
            buf ^= 1;
        }
    }

    const int ncol = n0 + tx * 4;
    float4 bv = *(const float4*)(bias + ncol);
#pragma unroll
    for (int i = 0; i < 8; i++) {
        int m = ty * 8 + i;
        int row = (t0 + (m >> 6)) * BATCH + (m & 63);
        float2 p0 = unpack2(acc[i][0]);
        float2 p1 = unpack2(acc[i][1]);
        float4 o;
        o.x = p0.x + bv.x; o.y = p0.y + bv.y;
        o.z = p1.x + bv.z; o.w = p1.y + bv.w;
        *(float4*)(g_xp + (size_t)row * G4 + ncol) = o;
    }
}

// ================================================================
// Kernel 2: backward-direction last hidden state (single step from 0).
// ================================================================
__global__ void __launch_bounds__(256) bwd_last_kernel(
    const float* __restrict__ x,
    const float* __restrict__ Wb, const float* __restrict__ bb)
{
    __shared__ float xs[IDIM];
    const int b = blockIdx.x, tid = threadIdx.x;
    xs[tid] = fmaxf(x[((size_t)b * SEQ + (SEQ - 1)) * IDIM + tid], 0.f);
    __syncthreads();

    const int j = blockIdx.y * 256 + tid;
    const int cols[3] = { j, 2 * HDIM + j, 3 * HDIM + j };    // i, g, o
    float acc[3] = { bb[cols[0]], bb[cols[1]], bb[cols[2]] };
#pragma unroll
    for (int gi = 0; gi < 3; gi++) {
        const float4* wp = (const float4*)(Wb + (size_t)cols[gi] * IDIM);
        float s = 0.f;
#pragma unroll 8
        for (int k4 = 0; k4 < IDIM / 4; k4++) {
            float4 w = __ldg(wp + k4);
            float4 xv = *(const float4*)&xs[k4 * 4];
            s += w.x * xv.x + w.y * xv.y + w.z * xv.z + w.w * xv.w;
        }
        acc[gi] += s;
    }
    float cst = sigf(acc[0]) * tanhf_fast(acc[1]);
    float h   = sigf(acc[2]) * tanhf_fast(cst);
    g_last[b * (2 * HDIM) + HDIM + j] = h;
}

// ================================================================
// Kernel 3: persistent forward LSTM scan, 2-D partition + K-SPLIT.
// 128 blocks = 4 batch-groups (bg=bid>>5) x 32 j-groups (jg=bid&31).
// Block: 16 H-cols (64 gate cols) x 16 batches. 512 threads:
// kh = tid>>8 selects k-half; each thread does the reuse-optimal
// 2 cols x 2 batches microtile over 256 k values (half the chain
// length, double the warps/SMSP for latency hiding; fma/crossbar
// volume unchanged). Halves are summed in the update phase via
// gs2[2][16][GSP]. Per-group flag barrier (32 blocks), absolute
// monotonic targets, reset kernel after scan (replay-safe).
// ================================================================
#define SCAN_BLOCKS 128
#define SCAN_THREADS 512
#define HSP 514                           // conflict-free spread; rows 8B-aligned
#define GSP 68
#define SCAN_SMEM ((64*HDIM + 16*HSP + 2*16*GSP) * 4)

__global__ void __launch_bounds__(SCAN_THREADS, 1) lstm_scan_kernel(const float* __restrict__ Whh)
{
    extern __shared__ float sm[];
    float* ws  = sm;                      // [128 kc][256] W slice, interleaved
    float* hs  = sm + 64 * HDIM;          // [16][HSP] staged h
    float* gs2 = hs + 16 * HSP;           // [2][16][GSP] per-half gate partials

    const int tid = threadIdx.x;
    const int bid = blockIdx.x;
    const int bg  = bid >> 5;             // 0..3   -> batches [bg*16, bg*16+16)
    const int jg  = bid & 31;             // 0..31  -> H-cols [jg*16, jg*16+16)
    const int fbase = bg * 32;            // this group's flag rows
    const int lane  = tid & 31;

    // ---- one-time W_hh slice load, interleaved conflict-free layout ----
    // ws[kc*256 + (lc&1)*128 + (lc>>1)*4 + e] = Whh[grow(lc)][kc*4+e]
    for (int u = tid; u < 64 * (HDIM / 4); u += SCAN_THREADS) {
        int lc = u & 63;                  // local gate col 0..63
        int kc = u >> 6;                  // k-chunk 0..127
        int gate = lc >> 4, jl = lc & 15;
        int grow = gate * HDIM + jg * 16 + jl;
        float4 w = *(const float4*)(Whh + (size_t)grow * HDIM + kc * 4);
        float* dst = ws + kc * 256 + (lc & 1) * 128 + (lc >> 1) * 4;
        dst[0] = w.x; dst[1] = w.y; dst[2] = w.z; dst[3] = w.w;
    }

    // ---- dot role: kh = k-half, (cp, bp) microtile as before ----
    const int kh = tid >> 8;              // 0,1
    const int r  = tid & 255;
    const int cp = r >> 3, bp = r & 7;
    const int lc0 = 2 * cp, lc1 = 2 * cp + 1;
    const int lb0 = 2 * bp, lb1 = 2 * bp + 1;
    const float* wev = ws + kh * 64 * 256 + cp * 4;   // this half's 64 kc
    const ull* hq0 = (const ull*)(hs + lb0 * HSP) + kh * 128;
    const ull* hq1 = (const ull*)(hs + lb1 * HSP) + kh * 128;
    float* gsh = gs2 + kh * 16 * GSP;

    // ---- update role (tid < 256): thread owns (batch ub, j-col uj) ----
    const int ub = tid >> 4, uj = tid & 15;           // valid for tid<256
    const int batch = bg * 16 + ub;
    const int jcol  = jg * 16 + uj;
    float cstate = 0.f;
    float* hout0 = &g_h[0][batch * HDIM + jcol];
    float* hout1 = &g_h[1][batch * HDIM + jcol];
    const size_t tstride = (size_t)BATCH * G4;
    const float* xpi = g_xp + (size_t)batch * G4 + 0 * HDIM + jcol;
    const float* xpf = g_xp + (size_t)batch * G4 + 1 * HDIM + jcol;
    const float* xpg = g_xp + (size_t)batch * G4 + 2 * HDIM + jcol;
    const float* xpo = g_xp + (size_t)batch * G4 + 3 * HDIM + jcol;
    float xvi = 0.f, xvf = 0.f, xvg = 0.f, xvo = 0.f;
    if (tid < 256) {
        xvi = __ldcs(xpi); xvf = __ldcs(xpf);
        xvg = __ldcs(xpg); xvo = __ldcs(xpo);
    }

    // ---- t = 0: h = 0 -> gates = xp, update directly ----
    if (tid < 256) {
        float i_ = sigf(xvi), f_ = sigf(xvf);
        float gv = tanhf_fast(xvg), o_ = sigf(xvo);
        cstate = fmaf(f_, cstate, i_ * gv);
        float h = o_ * tanhf_fast(cstate);
        __stcg(hout1, h);
        xvi = __ldcs(xpi + tstride); xvf = __ldcs(xpf + tstride);
        xvg = __ldcs(xpg + tstride); xvo = __ldcs(xpo + tstride);
    }

    // Group barrier: sync (drain h stores), leader release, every warp
    // polls the 32 group flags (one per lane), reconverge via syncwarp.
#define FLAGBAR(VAL) do{                                                       \
    __syncthreads();                                                           \
    if (tid == 0)                                                              \
        asm volatile("st.release.gpu.global.u64 [%0], %1;"                     \
                     :: "l"(&g_flags[bid][0]), "l"((ull)(VAL)) : "memory");    \
    {                                                                          \
        ull v;                                                                 \
        do {                                                                   \
            asm volatile("ld.acquire.gpu.global.u64 %0, [%1];"                 \
                         : "=l"(v) : "l"(&g_flags[fbase + lane][0]) : "memory"); \
        } while (v < (ull)(VAL));                                              \
        __syncwarp();                                                          \
    }                                                                          \
}while(0)

    FLAGBAR(1);

#pragma unroll 1
    for (int t = 1; t < SEQ; t++) {
        const ulonglong2* src = (const ulonglong2*)(g_h[t & 1] + (size_t)bg * 16 * HDIM);
        float* hdst = (t & 1) ? hout0 : hout1;

        // ---- stage 16 h rows (32 KB): 4x16B per thread, 8B STS ----
#pragma unroll
        for (int i = 0; i < 4; i++) {
            int u = tid + i * SCAN_THREADS;        // 16B chunk index (0..2047)
            ulonglong2 v = __ldcg(src + u);
            int b  = u >> 7;                       // 128 x 16B per batch row
            int kq = (u & 127) << 2;               // float offset (multiple of 4)
            ull* d = (ull*)(hs + b * HSP + kq);    // 8B-aligned
            d[0] = v.x; d[1] = v.y;
        }
        __syncthreads();

        // ---- half-k dot products (64 kc per thread) ----
        ull a000 = 0, a001 = 0, a010 = 0, a011 = 0;
        ull a100 = 0, a101 = 0, a110 = 0, a111 = 0;
#pragma unroll 8
        for (int kc = 0; kc < 64; kc++) {
            ulonglong2 W0 = *(const ulonglong2*)(wev + kc * 256);          // even col
            ulonglong2 W1 = *(const ulonglong2*)(wev + kc * 256 + 128);    // odd col
            ull h00 = hq0[kc * 2], h01 = hq0[kc * 2 + 1];
            ull h10 = hq1[kc * 2], h11 = hq1[kc * 2 + 1];
            ffma2(a000, h00, W0.x); ffma2(a001, h01, W0.y);
            ffma2(a010, h00, W1.x); ffma2(a011, h01, W1.y);
            ffma2(a100, h10, W0.x); ffma2(a101, h11, W0.y);
            ffma2(a110, h10, W1.x); ffma2(a111, h11, W1.y);
        }
        {
            float2 p; float s00, s01, s10, s11;
            p = unpack2(a000); s00 = p.x + p.y; p = unpack2(a001); s00 += p.x + p.y;
            p = unpack2(a010); s01 = p.x + p.y; p = unpack2(a011); s01 += p.x + p.y;
            p = unpack2(a100); s10 = p.x + p.y; p = unpack2(a101); s10 += p.x + p.y;
            p = unpack2(a110); s11 = p.x + p.y; p = unpack2(a111); s11 += p.x + p.y;
            gsh[lb0 * GSP + lc0] = s00; gsh[lb0 * GSP + lc1] = s01;
            gsh[lb1 * GSP + lc0] = s10; gsh[lb1 * GSP + lc1] = s11;
        }
        __syncthreads();

        // ---- update (tid < 256): sum halves + xp, activate ----
        if (tid < 256) {
            const float* g0 = gs2 + ub * GSP;
            const float* g1 = gs2 + 16 * GSP + ub * GSP;
            float gi = g0[ 0 + uj] + g1[ 0 + uj] + xvi;
            float gf = g0[16 + uj] + g1[16 + uj] + xvf;
            float gg = g0[32 + uj] + g1[32 + uj] + xvg;
            float go = g0[48 + uj] + g1[48 + uj] + xvo;
            float i_ = sigf(gi), f_ = sigf(gf);
            float gv = tanhf_fast(gg), o_ = sigf(go);
            cstate = fmaf(f_, cstate, i_ * gv);
            float h = o_ * tanhf_fast(cstate);
            __stcg(hdst, h);
            if (t == SEQ - 1)
                g_last[batch * (2 * HDIM) + jcol] = h;
            else {
                const size_t off = tstride * (size_t)(t + 1);
                xvi = __ldcs(xpi + off); xvf = __ldcs(xpf + off);
                xvg = __ldcs(xpg + off); xvo = __ldcs(xpo + off);
            }
        }

        if (t < SEQ - 1)
            FLAGBAR(t + 1);
    }
}

// ================================================================
// Kernel 3b: reset barrier flags (stream-ordered after the scan)
// so the next launch / graph replay starts from zero.
// ================================================================
__global__ void reset_flags_kernel()
{
    if (threadIdx.x < 128) g_flags[threadIdx.x][0] = 0ull;
}

// ================================================================
// Kernel 4: final FC. 64 blocks x 512 threads, 4 threads/output.
// ================================================================
__global__ void __launch_bounds__(512) fc_kernel(
    const float* __restrict__ Wfc, const float* __restrict__ bfc,
    float* __restrict__ out)
{
    __shared__ float ls[2 * HDIM];
    const int b = blockIdx.x, tid = threadIdx.x;
    if (tid < 256)
        ((float4*)ls)[tid] = ((const float4*)(g_last + (size_t)b * 2 * HDIM))[tid];
    __syncthreads();

    const int o = tid >> 2, q = tid & 3;
    const float4* wp = (const float4*)(Wfc + (size_t)o * (2 * HDIM)) + q * 64;
    const float4* lv = (const float4*)ls + q * 64;
    float acc = 0.f;
#pragma unroll 16
    for (int k = 0; k < 64; k++) {
        float4 w = __ldg(wp + k);
        float4 l = lv[k];
        acc += w.x * l.x + w.y * l.y + w.z * l.z + w.w * l.w;
    }
    acc += __shfl_xor_sync(0xffffffff, acc, 1);
    acc += __shfl_xor_sync(0xffffffff, acc, 2);
    if (q == 0) out[b * ODIM + o] = acc + bfc[o];
}

// ================================================================
extern "C" void kernel_launch(void* const* d_in, const int* in_sizes, int n_in,
                              void* d_out, int out_size)
{
    const float* x      = (const float*)d_in[0];
    const float* W_ih_f = (const float*)d_in[1];
    const float* W_hh_f = (const float*)d_in[2];
    const float* b_f    = (const float*)d_in[3];
    const float* W_ih_b = (const float*)d_in[4];
    const float* b_b    = (const float*)d_in[6];
    const float* W_fc   = (const float*)d_in[7];
    const float* b_fc   = (const float*)d_in[8];
    float* out = (float*)d_out;

    cudaFuncSetAttribute(gemm_xp_kernel,
                         cudaFuncAttributeMaxDynamicSharedMemorySize, GEMM_SMEM);
    cudaFuncSetAttribute(lstm_scan_kernel,
                         cudaFuncAttributeMaxDynamicSharedMemorySize, SCAN_SMEM);

    gemm_xp_kernel<<<dim3(G4 / BN, SEQ / 2), 256, GEMM_SMEM>>>(x, W_ih_f, b_f);
    bwd_last_kernel<<<dim3(BATCH, 2), 256>>>(x, W_ih_b, b_b);
    lstm_scan_kernel<<<SCAN_BLOCKS, SCAN_THREADS, SCAN_SMEM>>>(W_hh_f);
    reset_flags_kernel<<<1, 128>>>();
    fc_kernel<<<BATCH, 512>>>(W_fc, b_fc, out);
}

// round 10
// speedup vs baseline: 1.9553x; 1.9553x over previous
#include <cuda_runtime.h>
#include <cuda_bf16.h>
#include <cstdint>

#define BATCH 64
#define SEQ   1024
#define IDIM  256
#define HDIM  512
#define ODIM  128
#define G4    2048

typedef unsigned long long ull;

// ---------------- device scratch ----------------
__device__ float g_xp[(size_t)SEQ * BATCH * G4];          // input projection [t*64+b][4H]
__device__ __nv_bfloat16 g_hh[2][BATCH * HDIM];           // h hi plane, double-buffered
__device__ __nv_bfloat16 g_hl[2][BATCH * HDIM];           // h lo plane
__device__ float g_last[BATCH * 2 * HDIM];
__device__ ull g_flags[128][16];                          // padded barrier flags

__device__ __forceinline__ void ffma2(ull &acc, ull a, ull b) {
    asm("fma.rn.f32x2 %0, %1, %2, %0;" : "+l"(acc) : "l"(a), "l"(b));
}
__device__ __forceinline__ float2 unpack2(ull v) {
    float2 f; asm("mov.b64 {%0, %1}, %2;" : "=f"(f.x), "=f"(f.y) : "l"(v)); return f;
}
__device__ __forceinline__ ull dup2(float a) {
    ull r; asm("mov.b64 %0, {%1, %1};" : "=l"(r) : "f"(a)); return r;
}
__device__ __forceinline__ float sigf(float v) {
    return __fdividef(1.0f, 1.0f + __expf(-v));
}
__device__ __forceinline__ float tanhf_fast(float v) {
    float e = __expf(2.0f * v);
    return __fdividef(e - 1.0f, e + 1.0f);
}
__device__ __forceinline__ uint32_t packbf2(__nv_bfloat16 lo_elem, __nv_bfloat16 hi_elem) {
    // low 16 bits = element k (first), high 16 = element k+1
    return (uint32_t)__bfloat16_as_ushort(lo_elem) |
           ((uint32_t)__bfloat16_as_ushort(hi_elem) << 16);
}
__device__ __forceinline__ void mma16816(
    float& d0, float& d1, float& d2, float& d3,
    uint32_t a0, uint32_t a1, uint32_t a2, uint32_t a3,
    uint32_t b0, uint32_t b1)
{
    asm volatile(
        "mma.sync.aligned.m16n8k16.row.col.f32.bf16.bf16.f32 "
        "{%0,%1,%2,%3},{%4,%5,%6,%7},{%8,%9},{%0,%1,%2,%3};"
        : "+f"(d0), "+f"(d1), "+f"(d2), "+f"(d3)
        : "r"(a0), "r"(a1), "r"(a2), "r"(a3), "r"(b0), "r"(b1));
}

// ================================================================
// Kernel 1: xp = relu(x) @ W_ih_f^T + b_f  (unchanged from R9)
// ================================================================
#define BM 128
#define BN 64
#define BK 32
#define ALD 132
#define BLD 68
#define GEMM_SMEM ((2*BK*ALD + 2*BK*BLD) * 4)

__global__ void __launch_bounds__(256, 2) gemm_xp_kernel(
    const float* __restrict__ x,
    const float* __restrict__ Wih, const float* __restrict__ bias)
{
    extern __shared__ float smg[];
    float* As = smg;
    float* Bs = smg + 2 * BK * ALD;

    const int tid = threadIdx.x;
    const int n0  = blockIdx.x * BN;
    const int t0  = blockIdx.y * 2;
    const int tx  = tid & 15;
    const int ty  = tid >> 4;

    const int mA = tid >> 3, kqA = tid & 7;
    const float* aptr[4];
#pragma unroll
    for (int i = 0; i < 4; i++) {
        int m = mA + i * 32;
        aptr[i] = x + ((size_t)(m & 63) * SEQ + t0 + (m >> 6)) * IDIM + kqA * 4;
    }
    const int nB = tid >> 3, kqB = tid & 7;
    const float* bptr[2];
#pragma unroll
    for (int i = 0; i < 2; i++)
        bptr[i] = Wih + (size_t)(n0 + nB + i * 32) * IDIM + kqB * 4;

    ull acc[8][2];
#pragma unroll
    for (int i = 0; i < 8; i++) { acc[i][0] = 0; acc[i][1] = 0; }

    float4 ra[4], rb[2];
#pragma unroll
    for (int i = 0; i < 4; i++) ra[i] = *(const float4*)(aptr[i]);
#pragma unroll
    for (int i = 0; i < 2; i++) rb[i] = *(const float4*)(bptr[i]);

#define STSAB(BUF) do{                                                     \
    float* ab = As + (BUF) * BK * ALD;                                     \
    _Pragma("unroll") for (int i = 0; i < 4; i++) {                        \
        int m = mA + i * 32;                                               \
        ab[(kqA*4+0)*ALD + m] = fmaxf(ra[i].x, 0.f);                       \
        ab[(kqA*4+1)*ALD + m] = fmaxf(ra[i].y, 0.f);                       \
        ab[(kqA*4+2)*ALD + m] = fmaxf(ra[i].z, 0.f);                       \
        ab[(kqA*4+3)*ALD + m] = fmaxf(ra[i].w, 0.f); }                     \
    float* bb = Bs + (BUF) * BK * BLD;                                     \
    _Pragma("unroll") for (int i = 0; i < 2; i++) {                        \
        int n = nB + i * 32;                                               \
        bb[(kqB*4+0)*BLD + n] = rb[i].x; bb[(kqB*4+1)*BLD + n] = rb[i].y;  \
        bb[(kqB*4+2)*BLD + n] = rb[i].z; bb[(kqB*4+3)*BLD + n] = rb[i].w; }\
}while(0)

    STSAB(0);
    __syncthreads();

    int buf = 0;
#pragma unroll 1
    for (int it = 0; it < 8; it++) {
        if (it < 7) {
#pragma unroll
            for (int i = 0; i < 4; i++) ra[i] = *(const float4*)(aptr[i] + (it + 1) * BK);
#pragma unroll
            for (int i = 0; i < 2; i++) rb[i] = *(const float4*)(bptr[i] + (it + 1) * BK);
        }
        {
            const float* ab = As + buf * BK * ALD + ty * 8;
            const float* bb = Bs + buf * BK * BLD + tx * 4;
#pragma unroll
            for (int k = 0; k < BK; k++) {
                float4 a0 = *(const float4*)(ab + k * ALD);
                float4 a1 = *(const float4*)(ab + k * ALD + 4);
                ulonglong2 bq = *(const ulonglong2*)(bb + k * BLD);
                ull ad;
                ad = dup2(a0.x); ffma2(acc[0][0], ad, bq.x); ffma2(acc[0][1], ad, bq.y);
                ad = dup2(a0.y); ffma2(acc[1][0], ad, bq.x); ffma2(acc[1][1], ad, bq.y);
                ad = dup2(a0.z); ffma2(acc[2][0], ad, bq.x); ffma2(acc[2][1], ad, bq.y);
                ad = dup2(a0.w); ffma2(acc[3][0], ad, bq.x); ffma2(acc[3][1], ad, bq.y);
                ad = dup2(a1.x); ffma2(acc[4][0], ad, bq.x); ffma2(acc[4][1], ad, bq.y);
                ad = dup2(a1.y); ffma2(acc[5][0], ad, bq.x); ffma2(acc[5][1], ad, bq.y);
                ad = dup2(a1.z); ffma2(acc[6][0], ad, bq.x); ffma2(acc[6][1], ad, bq.y);
                ad = dup2(a1.w); ffma2(acc[7][0], ad, bq.x); ffma2(acc[7][1], ad, bq.y);
            }
        }
        if (it < 7) {
            STSAB(buf ^ 1);
            __syncthreads();
            buf ^= 1;
        }
    }

    const int ncol = n0 + tx * 4;
    float4 bv = *(const float4*)(bias + ncol);
#pragma unroll
    for (int i = 0; i < 8; i++) {
        int m = ty * 8 + i;
        int row = (t0 + (m >> 6)) * BATCH + (m & 63);
        float2 p0 = unpack2(acc[i][0]);
        float2 p1 = unpack2(acc[i][1]);
        float4 o;
        o.x = p0.x + bv.x; o.y = p0.y + bv.y;
        o.z = p1.x + bv.z; o.w = p1.y + bv.w;
        *(float4*)(g_xp + (size_t)row * G4 + ncol) = o;
    }
}

// ================================================================
// Kernel 2: backward-direction last hidden state (unchanged)
// ================================================================
__global__ void __launch_bounds__(256) bwd_last_kernel(
    const float* __restrict__ x,
    const float* __restrict__ Wb, const float* __restrict__ bb)
{
    __shared__ float xs[IDIM];
    const int b = blockIdx.x, tid = threadIdx.x;
    xs[tid] = fmaxf(x[((size_t)b * SEQ + (SEQ - 1)) * IDIM + tid], 0.f);
    __syncthreads();

    const int j = blockIdx.y * 256 + tid;
    const int cols[3] = { j, 2 * HDIM + j, 3 * HDIM + j };
    float acc[3] = { bb[cols[0]], bb[cols[1]], bb[cols[2]] };
#pragma unroll
    for (int gi = 0; gi < 3; gi++) {
        const float4* wp = (const float4*)(Wb + (size_t)cols[gi] * IDIM);
        float s = 0.f;
#pragma unroll 8
        for (int k4 = 0; k4 < IDIM / 4; k4++) {
            float4 w = __ldg(wp + k4);
            float4 xv = *(const float4*)&xs[k4 * 4];
            s += w.x * xv.x + w.y * xv.y + w.z * xv.z + w.w * xv.w;
        }
        acc[gi] += s;
    }
    float cst = sigf(acc[0]) * tanhf_fast(acc[1]);
    float h   = sigf(acc[2]) * tanhf_fast(cst);
    g_last[b * (2 * HDIM) + HDIM + j] = h;
}

// ================================================================
// Kernel 3: persistent LSTM scan — TENSOR CORE dots.
// 128 blocks = 4 batch-groups x 32 j-groups; 256 threads (8 warps).
// Per-block per-step GEMM [16 x 512] x [512 x 64] via
// mma.sync.m16n8k16 bf16 with hi/lo split (3 MMAs):
//   gates = h_hi*W_hi + h_lo*W_hi + h_hi*W_lo   (fp32 accum)
// W split into SMEM once (hi+lo bf16, 128 KB). h exchanged as
// hi/lo bf16 global planes, staged into SMEM per step (32 KB).
// Warp w: k-half kh=w>>2 (16 k-tiles), n-group nw=w&3 (16 cols =
// 2 n-tiles); two gs planes (per k-half) summed in update phase.
// Stride 260 words: conflict-free fragment LDS + 16B-aligned rows.
// ================================================================
#define SCAN_BLOCKS 128
#define SCAN_THREADS 256
#define WST 260                 // words per 512-elem bf16 row (256 + 4 pad)
#define GSP 68
#define SCAN_SMEM ((2*64*WST + 2*16*WST + 2*16*GSP) * 4)

__global__ void __launch_bounds__(SCAN_THREADS, 1) lstm_scan_kernel(const float* __restrict__ Whh)
{
    extern __shared__ uint32_t smw[];
    uint32_t* ws_hi = smw;                    // [64][WST]  W hi plane (bf16x2 words)
    uint32_t* ws_lo = smw + 64 * WST;         // [64][WST]  W lo plane
    uint32_t* hs_hi = smw + 2 * 64 * WST;     // [16][WST]  h hi plane
    uint32_t* hs_lo = hs_hi + 16 * WST;       // [16][WST]  h lo plane
    float*    gs2   = (float*)(hs_lo + 16 * WST);  // [2][16][GSP] per-k-half gates

    const int tid  = threadIdx.x;
    const int bid  = blockIdx.x;
    const int bg   = bid >> 5;                // batch group
    const int jg   = bid & 31;                // j group
    const int fbase = bg * 32;
    const int lane = tid & 31;
    const int wid  = tid >> 5;

    // ---- one-time W_hh slice load + hi/lo bf16 split ----
    // iteration it = col lc; threads cover the 256 words of that col.
#pragma unroll 1
    for (int u = tid; u < 64 * 256; u += SCAN_THREADS) {
        int lc = u >> 8;                     // local gate col 0..63
        int w  = u & 255;                    // word (2 k-elems)
        int grow = (lc >> 4) * HDIM + jg * 16 + (lc & 15);
        float2 v = *(const float2*)(Whh + (size_t)grow * HDIM + w * 2);
        __nv_bfloat16 h0 = __float2bfloat16(v.x);
        __nv_bfloat16 h1 = __float2bfloat16(v.y);
        __nv_bfloat16 l0 = __float2bfloat16(v.x - __bfloat162float(h0));
        __nv_bfloat16 l1 = __float2bfloat16(v.y - __bfloat162float(h1));
        ws_hi[lc * WST + w] = packbf2(h0, h1);
        ws_lo[lc * WST + w] = packbf2(l0, l1);
    }

    // ---- MMA role constants ----
    const int g   = lane >> 2, tig = lane & 3;
    const int kh  = wid >> 2;                // k-half 0/1
    const int nw  = wid & 3;                 // n-group (16 cols)
    const int nc0 = nw * 16;
    const int hb0 = g * WST + tig;
    const int hb1 = (g + 8) * WST + tig;
    const int wb0 = (nc0 + g) * WST + tig;       // n-tile 0 col
    const int wb1 = (nc0 + 8 + g) * WST + tig;   // n-tile 1 col
    const int kw0 = kh * 128;                // starting word of this k-half
    float* gso = gs2 + kh * 16 * GSP;

    // ---- update role ----
    const int ub = tid >> 4, uj = tid & 15;
    const int batch = bg * 16 + ub;
    const int jcol  = jg * 16 + uj;
    float cstate = 0.f;
    __nv_bfloat16* hh0 = &g_hh[0][batch * HDIM + jcol];
    __nv_bfloat16* hh1 = &g_hh[1][batch * HDIM + jcol];
    __nv_bfloat16* hl0 = &g_hl[0][batch * HDIM + jcol];
    __nv_bfloat16* hl1 = &g_hl[1][batch * HDIM + jcol];
    const size_t tstride = (size_t)BATCH * G4;
    const float* xpi = g_xp + (size_t)batch * G4 + 0 * HDIM + jcol;
    const float* xpf = g_xp + (size_t)batch * G4 + 1 * HDIM + jcol;
    const float* xpg = g_xp + (size_t)batch * G4 + 2 * HDIM + jcol;
    const float* xpo = g_xp + (size_t)batch * G4 + 3 * HDIM + jcol;
    float xvi = __ldcs(xpi), xvf = __ldcs(xpf);
    float xvg = __ldcs(xpg), xvo = __ldcs(xpo);

    // ---- t = 0: h = 0 -> gates = xp ----
    {
        float i_ = sigf(xvi), f_ = sigf(xvf);
        float gv = tanhf_fast(xvg), o_ = sigf(xvo);
        cstate = fmaf(f_, cstate, i_ * gv);
        float h = o_ * tanhf_fast(cstate);
        __nv_bfloat16 hhi = __float2bfloat16(h);
        __nv_bfloat16 hlo = __float2bfloat16(h - __bfloat162float(hhi));
        *hh1 = hhi; *hl1 = hlo;
        xvi = __ldcs(xpi + tstride); xvf = __ldcs(xpf + tstride);
        xvg = __ldcs(xpg + tstride); xvo = __ldcs(xpo + tstride);
    }

#define FLAGBAR(VAL) do{                                                       \
    __syncthreads();                                                           \
    if (tid == 0)                                                              \
        asm volatile("st.release.gpu.global.u64 [%0], %1;"                     \
                     :: "l"(&g_flags[bid][0]), "l"((ull)(VAL)) : "memory");    \
    {                                                                          \
        ull v;                                                                 \
        do {                                                                   \
            asm volatile("ld.acquire.gpu.global.u64 %0, [%1];"                 \
                         : "=l"(v) : "l"(&g_flags[fbase + lane][0]) : "memory"); \
        } while (v < (ull)(VAL));                                              \
        __syncwarp();                                                          \
    }                                                                          \
}while(0)

    FLAGBAR(1);

#pragma unroll 1
    for (int t = 1; t < SEQ; t++) {
        // ---- stage h hi/lo slab (16 batches): 4 x uint4 per thread per plane ----
        const uint4* srch = (const uint4*)(g_hh[t & 1] + (size_t)bg * 16 * HDIM);
        const uint4* srcl = (const uint4*)(g_hl[t & 1] + (size_t)bg * 16 * HDIM);
#pragma unroll
        for (int i = 0; i < 4; i++) {
            int u = tid + i * SCAN_THREADS;  // uint4 index: 64 per batch row
            int b  = u >> 6;
            int w0 = (u & 63) * 4;           // word offset (multiple of 4 -> 16B aligned)
            uint4 v = __ldcg(srch + u);
            *(uint4*)(hs_hi + b * WST + w0) = v;
            v = __ldcg(srcl + u);
            *(uint4*)(hs_lo + b * WST + w0) = v;
        }
        __syncthreads();

        // ---- tensor-core dots: 16 k-tiles x 2 n-tiles x 3 variants ----
        float D[6][4];
#pragma unroll
        for (int i = 0; i < 6; i++)
            D[i][0] = D[i][1] = D[i][2] = D[i][3] = 0.f;

#pragma unroll 4
        for (int j = 0; j < 16; j++) {
            int w = kw0 + j * 8;
            uint32_t ah0 = hs_hi[hb0 + w],     ah1 = hs_hi[hb1 + w];
            uint32_t ah2 = hs_hi[hb0 + w + 4], ah3 = hs_hi[hb1 + w + 4];
            uint32_t al0 = hs_lo[hb0 + w],     al1 = hs_lo[hb1 + w];
            uint32_t al2 = hs_lo[hb0 + w + 4], al3 = hs_lo[hb1 + w + 4];
            uint32_t bh00 = ws_hi[wb0 + w], bh01 = ws_hi[wb0 + w + 4];
            uint32_t bl00 = ws_lo[wb0 + w], bl01 = ws_lo[wb0 + w + 4];
            uint32_t bh10 = ws_hi[wb1 + w], bh11 = ws_hi[wb1 + w + 4];
            uint32_t bl10 = ws_lo[wb1 + w], bl11 = ws_lo[wb1 + w + 4];
            // n-tile 0
            mma16816(D[0][0], D[0][1], D[0][2], D[0][3], ah0, ah1, ah2, ah3, bh00, bh01);
            mma16816(D[1][0], D[1][1], D[1][2], D[1][3], al0, al1, al2, al3, bh00, bh01);
            mma16816(D[2][0], D[2][1], D[2][2], D[2][3], ah0, ah1, ah2, ah3, bl00, bl01);
            // n-tile 1
            mma16816(D[3][0], D[3][1], D[3][2], D[3][3], ah0, ah1, ah2, ah3, bh10, bh11);
            mma16816(D[4][0], D[4][1], D[4][2], D[4][3], al0, al1, al2, al3, bh10, bh11);
            mma16816(D[5][0], D[5][1], D[5][2], D[5][3], ah0, ah1, ah2, ah3, bl10, bl11);
        }

        // ---- epilogue: combine variants, store to this k-half's gs plane ----
        {
            float s0, s1, s2, s3;
            // n-tile 0 (cols nc0 + tig*2, +1)
            s0 = D[0][0] + D[1][0] + D[2][0];
            s1 = D[0][1] + D[1][1] + D[2][1];
            s2 = D[0][2] + D[1][2] + D[2][2];
            s3 = D[0][3] + D[1][3] + D[2][3];
            gso[g * GSP + nc0 + tig * 2 + 0] = s0;
            gso[g * GSP + nc0 + tig * 2 + 1] = s1;
            gso[(g + 8) * GSP + nc0 + tig * 2 + 0] = s2;
            gso[(g + 8) * GSP + nc0 + tig * 2 + 1] = s3;
            // n-tile 1 (cols nc0 + 8 + tig*2, +1)
            s0 = D[3][0] + D[4][0] + D[5][0];
            s1 = D[3][1] + D[4][1] + D[5][1];
            s2 = D[3][2] + D[4][2] + D[5][2];
            s3 = D[3][3] + D[4][3] + D[5][3];
            gso[g * GSP + nc0 + 8 + tig * 2 + 0] = s0;
            gso[g * GSP + nc0 + 8 + tig * 2 + 1] = s1;
            gso[(g + 8) * GSP + nc0 + 8 + tig * 2 + 0] = s2;
            gso[(g + 8) * GSP + nc0 + 8 + tig * 2 + 1] = s3;
        }
        __syncthreads();

        // ---- update: sum k-halves + xp, activate, split-store h ----
        {
            const float* g0 = gs2 + ub * GSP;
            const float* g1 = gs2 + 16 * GSP + ub * GSP;
            float gi = g0[ 0 + uj] + g1[ 0 + uj] + xvi;
            float gf = g0[16 + uj] + g1[16 + uj] + xvf;
            float gg = g0[32 + uj] + g1[32 + uj] + xvg;
            float go = g0[48 + uj] + g1[48 + uj] + xvo;
            float i_ = sigf(gi), f_ = sigf(gf);
            float gv = tanhf_fast(gg), o_ = sigf(go);
            cstate = fmaf(f_, cstate, i_ * gv);
            float h = o_ * tanhf_fast(cstate);
            __nv_bfloat16 hhi = __float2bfloat16(h);
            __nv_bfloat16 hlo = __float2bfloat16(h - __bfloat162float(hhi));
            if (t & 1) { *hh0 = hhi; *hl0 = hlo; }
            else       { *hh1 = hhi; *hl1 = hlo; }
            if (t == SEQ - 1)
                g_last[batch * (2 * HDIM) + jcol] = h;
            else {
                const size_t off = tstride * (size_t)(t + 1);
                xvi = __ldcs(xpi + off); xvf = __ldcs(xpf + off);
                xvg = __ldcs(xpg + off); xvo = __ldcs(xpo + off);
            }
        }

        if (t < SEQ - 1)
            FLAGBAR(t + 1);
    }
}

// ================================================================
// Kernel 3b: reset barrier flags (stream-ordered after the scan).
// ================================================================
__global__ void reset_flags_kernel()
{
    if (threadIdx.x < 128) g_flags[threadIdx.x][0] = 0ull;
}

// ================================================================
// Kernel 4: final FC (unchanged).
// ================================================================
__global__ void __launch_bounds__(512) fc_kernel(
    const float* __restrict__ Wfc, const float* __restrict__ bfc,
    float* __restrict__ out)
{
    __shared__ float ls[2 * HDIM];
    const int b = blockIdx.x, tid = threadIdx.x;
    if (tid < 256)
        ((float4*)ls)[tid] = ((const float4*)(g_last + (size_t)b * 2 * HDIM))[tid];
    __syncthreads();

    const int o = tid >> 2, q = tid & 3;
    const float4* wp = (const float4*)(Wfc + (size_t)o * (2 * HDIM)) + q * 64;
    const float4* lv = (const float4*)ls + q * 64;
    float acc = 0.f;
#pragma unroll 16
    for (int k = 0; k < 64; k++) {
        float4 w = __ldg(wp + k);
        float4 l = lv[k];
        acc += w.x * l.x + w.y * l.y + w.z * l.z + w.w * l.w;
    }
    acc += __shfl_xor_sync(0xffffffff, acc, 1);
    acc += __shfl_xor_sync(0xffffffff, acc, 2);
    if (q == 0) out[b * ODIM + o] = acc + bfc[o];
}

// ================================================================
extern "C" void kernel_launch(void* const* d_in, const int* in_sizes, int n_in,
                              void* d_out, int out_size)
{
    const float* x      = (const float*)d_in[0];
    const float* W_ih_f = (const float*)d_in[1];
    const float* W_hh_f = (const float*)d_in[2];
    const float* b_f    = (const float*)d_in[3];
    const float* W_ih_b = (const float*)d_in[4];
    const float* b_b    = (const float*)d_in[6];
    const float* W_fc   = (const float*)d_in[7];
    const float* b_fc   = (const float*)d_in[8];
    float* out = (float*)d_out;

    cudaFuncSetAttribute(gemm_xp_kernel,
                         cudaFuncAttributeMaxDynamicSharedMemorySize, GEMM_SMEM);
    cudaFuncSetAttribute(lstm_scan_kernel,
                         cudaFuncAttributeMaxDynamicSharedMemorySize, SCAN_SMEM);

    gemm_xp_kernel<<<dim3(G4 / BN, SEQ / 2), 256, GEMM_SMEM>>>(x, W_ih_f, b_f);
    bwd_last_kernel<<<dim3(BATCH, 2), 256>>>(x, W_ih_b, b_b);
    lstm_scan_kernel<<<SCAN_BLOCKS, SCAN_THREADS, SCAN_SMEM>>>(W_hh_f);
    reset_flags_kernel<<<1, 128>>>();
    fc_kernel<<<BATCH, 512>>>(W_fc, b_fc, out);
}

// round 11
// speedup vs baseline: 2.2262x; 1.1386x over previous
#include <cuda_runtime.h>
#include <cuda_bf16.h>
#include <cstdint>

#define BATCH 64
#define SEQ   1024
#define IDIM  256
#define HDIM  512
#define ODIM  128
#define G4    2048

typedef unsigned long long ull;

// ---------------- device scratch ----------------
__device__ float g_xp[(size_t)SEQ * BATCH * G4];          // input projection [t*64+b][4H]
__device__ __nv_bfloat16 g_hh[2][BATCH * HDIM];           // h hi plane, double-buffered
__device__ __nv_bfloat16 g_hl[2][BATCH * HDIM];           // h lo plane
__device__ float g_last[BATCH * 2 * HDIM];
__device__ ull g_flags[128][16];                          // padded barrier flags

__device__ __forceinline__ float sigf(float v) {
    return __fdividef(1.0f, 1.0f + __expf(-v));
}
__device__ __forceinline__ float tanhf_fast(float v) {
    float e = __expf(2.0f * v);
    return __fdividef(e - 1.0f, e + 1.0f);
}
__device__ __forceinline__ uint32_t packbf2(__nv_bfloat16 lo_elem, __nv_bfloat16 hi_elem) {
    return (uint32_t)__bfloat16_as_ushort(lo_elem) |
           ((uint32_t)__bfloat16_as_ushort(hi_elem) << 16);
}
__device__ __forceinline__ void mma16816(
    float& d0, float& d1, float& d2, float& d3,
    uint32_t a0, uint32_t a1, uint32_t a2, uint32_t a3,
    uint32_t b0, uint32_t b1)
{
    asm volatile(
        "mma.sync.aligned.m16n8k16.row.col.f32.bf16.bf16.f32 "
        "{%0,%1,%2,%3},{%4,%5,%6,%7},{%8,%9},{%0,%1,%2,%3};"
        : "+f"(d0), "+f"(d1), "+f"(d2), "+f"(d3)
        : "r"(a0), "r"(a1), "r"(a2), "r"(a3), "r"(b0), "r"(b1));
}

// ================================================================
// Kernel 1: xp = relu(x) @ W_ih_f^T + b_f  — TENSOR CORE version.
// M=65536 (rows m = t*64+b), N=2048, K=256.
// Block tile 128x64, K-chunks of 64; 8 warps, warp tile 32x32
// (2 m-tiles x 4 n-tiles). bf16 hi/lo split, 3 MMA variants all
// accumulated into the same fp32 C. relu fused into A staging.
// SMEM rows stride 36 words -> conflict-free fragment LDS.
// ================================================================
#define XBM 128
#define XBN 64
#define XBK 64
#define XST 36
#define XGEMM_SMEM ((2*XBM*XST + 2*XBN*XST) * 4)

__global__ void __launch_bounds__(256, 2) gemm_xp_kernel(
    const float* __restrict__ x,
    const float* __restrict__ Wih, const float* __restrict__ bias)
{
    extern __shared__ uint32_t smx[];
    uint32_t* Ah = smx;                       // [128][XST]
    uint32_t* Al = Ah + XBM * XST;
    uint32_t* Bh = Al + XBM * XST;            // [64][XST]
    uint32_t* Bl = Bh + XBN * XST;

    const int tid  = threadIdx.x;
    const int lane = tid & 31, wid = tid >> 5;
    const int n0 = blockIdx.x * XBN;
    const int t0 = blockIdx.y * 2;

    const int mw = wid >> 1;      // 0..3 (M warp)
    const int nw = wid & 1;       // 0..1 (N warp)
    const int g = lane >> 2, tig = lane & 3;

    float C[2][4][4];
#pragma unroll
    for (int mt = 0; mt < 2; mt++)
#pragma unroll
        for (int nt = 0; nt < 4; nt++)
            C[mt][nt][0] = C[mt][nt][1] = C[mt][nt][2] = C[mt][nt][3] = 0.f;

#pragma unroll 1
    for (int ko = 0; ko < IDIM; ko += XBK) {
        // ---- stage A (relu + hi/lo split): 8 float4 per thread ----
#pragma unroll
        for (int i = 0; i < 8; i++) {
            int u = tid + i * 256;
            int row = u >> 4, q = u & 15;          // row 0..127, q = float4 in row
            int b = row & 63, tt = t0 + (row >> 6);
            float4 v = __ldcg((const float4*)(x + ((size_t)b * SEQ + tt) * IDIM + ko + q * 4));
            v.x = fmaxf(v.x, 0.f); v.y = fmaxf(v.y, 0.f);
            v.z = fmaxf(v.z, 0.f); v.w = fmaxf(v.w, 0.f);
            __nv_bfloat16 h0 = __float2bfloat16(v.x), h1 = __float2bfloat16(v.y);
            __nv_bfloat16 h2 = __float2bfloat16(v.z), h3 = __float2bfloat16(v.w);
            __nv_bfloat16 l0 = __float2bfloat16(v.x - __bfloat162float(h0));
            __nv_bfloat16 l1 = __float2bfloat16(v.y - __bfloat162float(h1));
            __nv_bfloat16 l2 = __float2bfloat16(v.z - __bfloat162float(h2));
            __nv_bfloat16 l3 = __float2bfloat16(v.w - __bfloat162float(h3));
            *(uint2*)(Ah + row * XST + q * 2) = make_uint2(packbf2(h0, h1), packbf2(h2, h3));
            *(uint2*)(Al + row * XST + q * 2) = make_uint2(packbf2(l0, l1), packbf2(l2, l3));
        }
        // ---- stage B (hi/lo split): 4 float4 per thread ----
#pragma unroll
        for (int i = 0; i < 4; i++) {
            int u = tid + i * 256;
            int row = u >> 4, q = u & 15;          // row = gate col 0..63
            float4 v = __ldcg((const float4*)(Wih + (size_t)(n0 + row) * IDIM + ko + q * 4));
            __nv_bfloat16 h0 = __float2bfloat16(v.x), h1 = __float2bfloat16(v.y);
            __nv_bfloat16 h2 = __float2bfloat16(v.z), h3 = __float2bfloat16(v.w);
            __nv_bfloat16 l0 = __float2bfloat16(v.x - __bfloat162float(h0));
            __nv_bfloat16 l1 = __float2bfloat16(v.y - __bfloat162float(h1));
            __nv_bfloat16 l2 = __float2bfloat16(v.z - __bfloat162float(h2));
            __nv_bfloat16 l3 = __float2bfloat16(v.w - __bfloat162float(h3));
            *(uint2*)(Bh + row * XST + q * 2) = make_uint2(packbf2(h0, h1), packbf2(h2, h3));
            *(uint2*)(Bl + row * XST + q * 2) = make_uint2(packbf2(l0, l1), packbf2(l2, l3));
        }
        __syncthreads();

        // ---- MMA: 4 k16-steps x (2 m-tiles x 4 n-tiles x 3 variants) ----
#pragma unroll
        for (int ks = 0; ks < 4; ks++) {
            int w = ks * 8;
            uint32_t bh[4][2], bl[4][2];
#pragma unroll
            for (int nt = 0; nt < 4; nt++) {
                int c = (nw * 32 + nt * 8 + g) * XST + w + tig;
                bh[nt][0] = Bh[c]; bh[nt][1] = Bh[c + 4];
                bl[nt][0] = Bl[c]; bl[nt][1] = Bl[c + 4];
            }
#pragma unroll
            for (int mt = 0; mt < 2; mt++) {
                int r0 = (mw * 32 + mt * 16 + g) * XST + w + tig;
                int r1 = r0 + 8 * XST;
                uint32_t ah0 = Ah[r0], ah1 = Ah[r1], ah2 = Ah[r0 + 4], ah3 = Ah[r1 + 4];
                uint32_t al0 = Al[r0], al1 = Al[r1], al2 = Al[r0 + 4], al3 = Al[r1 + 4];
#pragma unroll
                for (int nt = 0; nt < 4; nt++) {
                    mma16816(C[mt][nt][0], C[mt][nt][1], C[mt][nt][2], C[mt][nt][3],
                             ah0, ah1, ah2, ah3, bh[nt][0], bh[nt][1]);
                    mma16816(C[mt][nt][0], C[mt][nt][1], C[mt][nt][2], C[mt][nt][3],
                             al0, al1, al2, al3, bh[nt][0], bh[nt][1]);
                    mma16816(C[mt][nt][0], C[mt][nt][1], C[mt][nt][2], C[mt][nt][3],
                             ah0, ah1, ah2, ah3, bl[nt][0], bl[nt][1]);
                }
            }
        }
        __syncthreads();
    }

    // ---- epilogue: bias + store float2 per fragment row ----
#pragma unroll
    for (int mt = 0; mt < 2; mt++) {
#pragma unroll
        for (int nt = 0; nt < 4; nt++) {
            int col = n0 + nw * 32 + nt * 8 + tig * 2;
            float2 bv = *(const float2*)(bias + col);
            int ml = mw * 32 + mt * 16 + g;
            int rowg = (t0 + (ml >> 6)) * BATCH + (ml & 63);
            float2 o0 = { C[mt][nt][0] + bv.x, C[mt][nt][1] + bv.y };
            *(float2*)(g_xp + (size_t)rowg * G4 + col) = o0;
            ml += 8;
            rowg = (t0 + (ml >> 6)) * BATCH + (ml & 63);
            float2 o1 = { C[mt][nt][2] + bv.x, C[mt][nt][3] + bv.y };
            *(float2*)(g_xp + (size_t)rowg * G4 + col) = o1;
        }
    }
}

// ================================================================
// Kernel 2: backward-direction last hidden state (unchanged)
// ================================================================
__global__ void __launch_bounds__(256) bwd_last_kernel(
    const float* __restrict__ x,
    const float* __restrict__ Wb, const float* __restrict__ bb)
{
    __shared__ float xs[IDIM];
    const int b = blockIdx.x, tid = threadIdx.x;
    xs[tid] = fmaxf(x[((size_t)b * SEQ + (SEQ - 1)) * IDIM + tid], 0.f);
    __syncthreads();

    const int j = blockIdx.y * 256 + tid;
    const int cols[3] = { j, 2 * HDIM + j, 3 * HDIM + j };
    float acc[3] = { bb[cols[0]], bb[cols[1]], bb[cols[2]] };
#pragma unroll
    for (int gi = 0; gi < 3; gi++) {
        const float4* wp = (const float4*)(Wb + (size_t)cols[gi] * IDIM);
        float s = 0.f;
#pragma unroll 8
        for (int k4 = 0; k4 < IDIM / 4; k4++) {
            float4 w = __ldg(wp + k4);
            float4 xv = *(const float4*)&xs[k4 * 4];
            s += w.x * xv.x + w.y * xv.y + w.z * xv.z + w.w * xv.w;
        }
        acc[gi] += s;
    }
    float cst = sigf(acc[0]) * tanhf_fast(acc[1]);
    float h   = sigf(acc[2]) * tanhf_fast(cst);
    g_last[b * (2 * HDIM) + HDIM + j] = h;
}

// ================================================================
// Kernel 3: persistent LSTM scan — TENSOR CORE dots (unchanged
// from round 10's passing version).
// ================================================================
#define SCAN_BLOCKS 128
#define SCAN_THREADS 256
#define WST 260
#define GSP 68
#define SCAN_SMEM ((2*64*WST + 2*16*WST + 2*16*GSP) * 4)

__global__ void __launch_bounds__(SCAN_THREADS, 1) lstm_scan_kernel(const float* __restrict__ Whh)
{
    extern __shared__ uint32_t smw[];
    uint32_t* ws_hi = smw;                    // [64][WST]
    uint32_t* ws_lo = smw + 64 * WST;
    uint32_t* hs_hi = smw + 2 * 64 * WST;     // [16][WST]
    uint32_t* hs_lo = hs_hi + 16 * WST;
    float*    gs2   = (float*)(hs_lo + 16 * WST);  // [2][16][GSP]

    const int tid  = threadIdx.x;
    const int bid  = blockIdx.x;
    const int bg   = bid >> 5;
    const int jg   = bid & 31;
    const int fbase = bg * 32;
    const int lane = tid & 31;
    const int wid  = tid >> 5;

#pragma unroll 1
    for (int u = tid; u < 64 * 256; u += SCAN_THREADS) {
        int lc = u >> 8;
        int w  = u & 255;
        int grow = (lc >> 4) * HDIM + jg * 16 + (lc & 15);
        float2 v = *(const float2*)(Whh + (size_t)grow * HDIM + w * 2);
        __nv_bfloat16 h0 = __float2bfloat16(v.x);
        __nv_bfloat16 h1 = __float2bfloat16(v.y);
        __nv_bfloat16 l0 = __float2bfloat16(v.x - __bfloat162float(h0));
        __nv_bfloat16 l1 = __float2bfloat16(v.y - __bfloat162float(h1));
        ws_hi[lc * WST + w] = packbf2(h0, h1);
        ws_lo[lc * WST + w] = packbf2(l0, l1);
    }

    const int g   = lane >> 2, tig = lane & 3;
    const int kh  = wid >> 2;
    const int nw  = wid & 3;
    const int nc0 = nw * 16;
    const int hb0 = g * WST + tig;
    const int hb1 = (g + 8) * WST + tig;
    const int wb0 = (nc0 + g) * WST + tig;
    const int wb1 = (nc0 + 8 + g) * WST + tig;
    const int kw0 = kh * 128;
    float* gso = gs2 + kh * 16 * GSP;

    const int ub = tid >> 4, uj = tid & 15;
    const int batch = bg * 16 + ub;
    const int jcol  = jg * 16 + uj;
    float cstate = 0.f;
    __nv_bfloat16* hh0 = &g_hh[0][batch * HDIM + jcol];
    __nv_bfloat16* hh1 = &g_hh[1][batch * HDIM + jcol];
    __nv_bfloat16* hl0 = &g_hl[0][batch * HDIM + jcol];
    __nv_bfloat16* hl1 = &g_hl[1][batch * HDIM + jcol];
    const size_t tstride = (size_t)BATCH * G4;
    const float* xpi = g_xp + (size_t)batch * G4 + 0 * HDIM + jcol;
    const float* xpf = g_xp + (size_t)batch * G4 + 1 * HDIM + jcol;
    const float* xpg = g_xp + (size_t)batch * G4 + 2 * HDIM + jcol;
    const float* xpo = g_xp + (size_t)batch * G4 + 3 * HDIM + jcol;
    float xvi = __ldcs(xpi), xvf = __ldcs(xpf);
    float xvg = __ldcs(xpg), xvo = __ldcs(xpo);

    {
        float i_ = sigf(xvi), f_ = sigf(xvf);
        float gv = tanhf_fast(xvg), o_ = sigf(xvo);
        cstate = fmaf(f_, cstate, i_ * gv);
        float h = o_ * tanhf_fast(cstate);
        __nv_bfloat16 hhi = __float2bfloat16(h);
        __nv_bfloat16 hlo = __float2bfloat16(h - __bfloat162float(hhi));
        *hh1 = hhi; *hl1 = hlo;
        xvi = __ldcs(xpi + tstride); xvf = __ldcs(xpf + tstride);
        xvg = __ldcs(xpg + tstride); xvo = __ldcs(xpo + tstride);
    }

#define FLAGBAR(VAL) do{                                                       \
    __syncthreads();                                                           \
    if (tid == 0)                                                              \
        asm volatile("st.release.gpu.global.u64 [%0], %1;"                     \
                     :: "l"(&g_flags[bid][0]), "l"((ull)(VAL)) : "memory");    \
    {                                                                          \
        ull v;                                                                 \
        do {                                                                   \
            asm volatile("ld.acquire.gpu.global.u64 %0, [%1];"                 \
                         : "=l"(v) : "l"(&g_flags[fbase + lane][0]) : "memory"); \
        } while (v < (ull)(VAL));                                              \
        __syncwarp();                                                          \
    }                                                                          \
}while(0)

    FLAGBAR(1);

#pragma unroll 1
    for (int t = 1; t < SEQ; t++) {
        const uint4* srch = (const uint4*)(g_hh[t & 1] + (size_t)bg * 16 * HDIM);
        const uint4* srcl = (const uint4*)(g_hl[t & 1] + (size_t)bg * 16 * HDIM);
#pragma unroll
        for (int i = 0; i < 4; i++) {
            int u = tid + i * SCAN_THREADS;
            int b  = u >> 6;
            int w0 = (u & 63) * 4;
            uint4 v = __ldcg(srch + u);
            *(uint4*)(hs_hi + b * WST + w0) = v;
            v = __ldcg(srcl + u);
            *(uint4*)(hs_lo + b * WST + w0) = v;
        }
        __syncthreads();

        float D[6][4];
#pragma unroll
        for (int i = 0; i < 6; i++)
            D[i][0] = D[i][1] = D[i][2] = D[i][3] = 0.f;

#pragma unroll 4
        for (int j = 0; j < 16; j++) {
            int w = kw0 + j * 8;
            uint32_t ah0 = hs_hi[hb0 + w],     ah1 = hs_hi[hb1 + w];
            uint32_t ah2 = hs_hi[hb0 + w + 4], ah3 = hs_hi[hb1 + w + 4];
            uint32_t al0 = hs_lo[hb0 + w],     al1 = hs_lo[hb1 + w];
            uint32_t al2 = hs_lo[hb0 + w + 4], al3 = hs_lo[hb1 + w + 4];
            uint32_t bh00 = ws_hi[wb0 + w], bh01 = ws_hi[wb0 + w + 4];
            uint32_t bl00 = ws_lo[wb0 + w], bl01 = ws_lo[wb0 + w + 4];
            uint32_t bh10 = ws_hi[wb1 + w], bh11 = ws_hi[wb1 + w + 4];
            uint32_t bl10 = ws_lo[wb1 + w], bl11 = ws_lo[wb1 + w + 4];
            mma16816(D[0][0], D[0][1], D[0][2], D[0][3], ah0, ah1, ah2, ah3, bh00, bh01);
            mma16816(D[1][0], D[1][1], D[1][2], D[1][3], al0, al1, al2, al3, bh00, bh01);
            mma16816(D[2][0], D[2][1], D[2][2], D[2][3], ah0, ah1, ah2, ah3, bl00, bl01);
            mma16816(D[3][0], D[3][1], D[3][2], D[3][3], ah0, ah1, ah2, ah3, bh10, bh11);
            mma16816(D[4][0], D[4][1], D[4][2], D[4][3], al0, al1, al2, al3, bh10, bh11);
            mma16816(D[5][0], D[5][1], D[5][2], D[5][3], ah0, ah1, ah2, ah3, bl10, bl11);
        }

        {
            float s0, s1, s2, s3;
            s0 = D[0][0] + D[1][0] + D[2][0];
            s1 = D[0][1] + D[1][1] + D[2][1];
            s2 = D[0][2] + D[1][2] + D[2][2];
            s3 = D[0][3] + D[1][3] + D[2][3];
            gso[g * GSP + nc0 + tig * 2 + 0] = s0;
            gso[g * GSP + nc0 + tig * 2 + 1] = s1;
            gso[(g + 8) * GSP + nc0 + tig * 2 + 0] = s2;
            gso[(g + 8) * GSP + nc0 + tig * 2 + 1] = s3;
            s0 = D[3][0] + D[4][0] + D[5][0];
            s1 = D[3][1] + D[4][1] + D[5][1];
            s2 = D[3][2] + D[4][2] + D[5][2];
            s3 = D[3][3] + D[4][3] + D[5][3];
            gso[g * GSP + nc0 + 8 + tig * 2 + 0] = s0;
            gso[g * GSP + nc0 + 8 + tig * 2 + 1] = s1;
            gso[(g + 8) * GSP + nc0 + 8 + tig * 2 + 0] = s2;
            gso[(g + 8) * GSP + nc0 + 8 + tig * 2 + 1] = s3;
        }
        __syncthreads();

        {
            const float* g0 = gs2 + ub * GSP;
            const float* g1 = gs2 + 16 * GSP + ub * GSP;
            float gi = g0[ 0 + uj] + g1[ 0 + uj] + xvi;
            float gf = g0[16 + uj] + g1[16 + uj] + xvf;
            float gg = g0[32 + uj] + g1[32 + uj] + xvg;
            float go = g0[48 + uj] + g1[48 + uj] + xvo;
            float i_ = sigf(gi), f_ = sigf(gf);
            float gv = tanhf_fast(gg), o_ = sigf(go);
            cstate = fmaf(f_, cstate, i_ * gv);
            float h = o_ * tanhf_fast(cstate);
            __nv_bfloat16 hhi = __float2bfloat16(h);
            __nv_bfloat16 hlo = __float2bfloat16(h - __bfloat162float(hhi));
            if (t & 1) { *hh0 = hhi; *hl0 = hlo; }
            else       { *hh1 = hhi; *hl1 = hlo; }
            if (t == SEQ - 1)
                g_last[batch * (2 * HDIM) + jcol] = h;
            else {
                const size_t off = tstride * (size_t)(t + 1);
                xvi = __ldcs(xpi + off); xvf = __ldcs(xpf + off);
                xvg = __ldcs(xpg + off); xvo = __ldcs(xpo + off);
            }
        }

        if (t < SEQ - 1)
            FLAGBAR(t + 1);
    }
}

// ================================================================
// Kernel 3b: reset barrier flags (stream-ordered after the scan).
// ================================================================
__global__ void reset_flags_kernel()
{
    if (threadIdx.x < 128) g_flags[threadIdx.x][0] = 0ull;
}

// ================================================================
// Kernel 4: final FC (unchanged).
// ================================================================
__global__ void __launch_bounds__(512) fc_kernel(
    const float* __restrict__ Wfc, const float* __restrict__ bfc,
    float* __restrict__ out)
{
    __shared__ float ls[2 * HDIM];
    const int b = blockIdx.x, tid = threadIdx.x;
    if (tid < 256)
        ((float4*)ls)[tid] = ((const float4*)(g_last + (size_t)b * 2 * HDIM))[tid];
    __syncthreads();

    const int o = tid >> 2, q = tid & 3;
    const float4* wp = (const float4*)(Wfc + (size_t)o * (2 * HDIM)) + q * 64;
    const float4* lv = (const float4*)ls + q * 64;
    float acc = 0.f;
#pragma unroll 16
    for (int k = 0; k < 64; k++) {
        float4 w = __ldg(wp + k);
        float4 l = lv[k];
        acc += w.x * l.x + w.y * l.y + w.z * l.z + w.w * l.w;
    }
    acc += __shfl_xor_sync(0xffffffff, acc, 1);
    acc += __shfl_xor_sync(0xffffffff, acc, 2);
    if (q == 0) out[b * ODIM + o] = acc + bfc[o];
}

// ================================================================
extern "C" void kernel_launch(void* const* d_in, const int* in_sizes, int n_in,
                              void* d_out, int out_size)
{
    const float* x      = (const float*)d_in[0];
    const float* W_ih_f = (const float*)d_in[1];
    const float* W_hh_f = (const float*)d_in[2];
    const float* b_f    = (const float*)d_in[3];
    const float* W_ih_b = (const float*)d_in[4];
    const float* b_b    = (const float*)d_in[6];
    const float* W_fc   = (const float*)d_in[7];
    const float* b_fc   = (const float*)d_in[8];
    float* out = (float*)d_out;

    cudaFuncSetAttribute(gemm_xp_kernel,
                         cudaFuncAttributeMaxDynamicSharedMemorySize, XGEMM_SMEM);
    cudaFuncSetAttribute(lstm_scan_kernel,
                         cudaFuncAttributeMaxDynamicSharedMemorySize, SCAN_SMEM);

    gemm_xp_kernel<<<dim3(G4 / XBN, SEQ / 2), 256, XGEMM_SMEM>>>(x, W_ih_f, b_f);
    bwd_last_kernel<<<dim3(BATCH, 2), 256>>>(x, W_ih_b, b_b);
    lstm_scan_kernel<<<SCAN_BLOCKS, SCAN_THREADS, SCAN_SMEM>>>(W_hh_f);
    reset_flags_kernel<<<1, 128>>>();
    fc_kernel<<<BATCH, 512>>>(W_fc, b_fc, out);
}